// round 3
// baseline (speedup 1.0000x reference)
#include <cuda_runtime.h>
#include <math.h>

#define N_ENT   14541
#define EMB_DIM 768
#define EMB_V4  192            // EMB_DIM / 4
#define TOP_K   1000
#define NEG_T   5
#define BS      128
#define MARGIN  0.5f

// Scratch (no cudaMalloc allowed)
__device__ float g_simi_mean[N_ENT];
__device__ float g_alpha[BS];

// ---------------------------------------------------------------------------
// Block reduce: valid result in thread 0.
// ---------------------------------------------------------------------------
__device__ __forceinline__ float block_reduce_sum(float v, float* sh) {
    #pragma unroll
    for (int o = 16; o > 0; o >>= 1) v += __shfl_down_sync(0xffffffffu, v, o);
    int wid = threadIdx.x >> 5;
    int lid = threadIdx.x & 31;
    if (lid == 0) sh[wid] = v;
    __syncthreads();
    int nw = blockDim.x >> 5;
    if (wid == 0) {
        v = (lid < nw) ? sh[lid] : 0.0f;
        #pragma unroll
        for (int o = 16; o > 0; o >>= 1) v += __shfl_down_sync(0xffffffffu, v, o);
    }
    return v;
}

// ---------------------------------------------------------------------------
// Kernel 1: per-row mean of simi_score_mtx. One block per row.
// At 87.7% DRAM utilization (6.95 TB/s) — at the HBM ceiling. Unchanged.
// ---------------------------------------------------------------------------
__global__ __launch_bounds__(256)
void row_mean_kernel(const float* __restrict__ simi) {
    __shared__ float sh[8];
    const int tid = threadIdx.x;
    const size_t e0 = (size_t)blockIdx.x * N_ENT;
    const size_t e1 = e0 + N_ENT;
    const size_t a0 = (e0 + 3) & ~(size_t)3;   // first 16B-aligned element
    const size_t a1 = e1 & ~(size_t)3;         // end of aligned region

    float s = 0.0f;
    for (size_t e = e0 + tid; e < a0; e += 256) s += simi[e];
    for (size_t e = a1 + tid; e < e1; e += 256) s += simi[e];

    const float4* __restrict__ v4 = (const float4*)(simi + a0);
    const int nv = (int)((a1 - a0) >> 2);
    float4 a = make_float4(0.f, 0.f, 0.f, 0.f);
    #pragma unroll 4
    for (int i = tid; i < nv; i += 256) {
        float4 x = v4[i];
        a.x += x.x; a.y += x.y; a.z += x.z; a.w += x.w;
    }
    s += (a.x + a.y) + (a.z + a.w);
    s = block_reduce_sum(s, sh);
    if (tid == 0) g_simi_mean[blockIdx.x] = s * (1.0f / (float)N_ENT);
}

// ---------------------------------------------------------------------------
// Kernel 2: per-sample alpha. One block (768 threads) per sample.
// Phase A: thread = (dim-group g in [0,96) -> dims [8g,8g+8), k-slice j in [0,8)).
//   Each thread loads 32B (two adjacent float4 = one full 32B sector) per row,
//   over rows k = j, j+8, ... (125 rows). 100% sector efficiency on the
//   random-row gather. The 8 k-slices of a group are consecutive lanes ->
//   combine via 3 shfl_xor steps; lane j==0 computes std for its 8 dims.
// Phase B: strided over k for the 5 score/simi feature groups.
// ---------------------------------------------------------------------------
__global__ __launch_bounds__(768)
void alpha_kernel(const int*   __restrict__ ent_idx,
                  const float* __restrict__ stelp_scores,
                  const float* __restrict__ rotate_scores,
                  const float* __restrict__ emb,
                  const float* __restrict__ proj_w,
                  const float* __restrict__ proj_b) {
    __shared__ int   s_idx[TOP_K];
    __shared__ float sh[24];

    const int b   = blockIdx.x;
    const int tid = threadIdx.x;

    for (int k = tid; k < TOP_K; k += 768)
        s_idx[k] = ent_idx[b * TOP_K + k];
    __syncthreads();

    // ---- Phase A: 32B-per-thread gather + sum/sumsq ----
    const int j = tid & 7;          // k-slice 0..7
    const int g = tid >> 3;         // dim group 0..95 (dims 8g..8g+7)
    const float4* __restrict__ emb4 = (const float4*)emb;

    float s0[4] = {0.f, 0.f, 0.f, 0.f}, s1[4] = {0.f, 0.f, 0.f, 0.f};
    float q0[4] = {0.f, 0.f, 0.f, 0.f}, q1[4] = {0.f, 0.f, 0.f, 0.f};
    #pragma unroll 2
    for (int k = j; k < TOP_K; k += 8) {    // exactly 125 iters for all j
        const float4* p = emb4 + (size_t)s_idx[k] * EMB_V4 + 2 * g;
        float4 v0 = __ldg(p);
        float4 v1 = __ldg(p + 1);
        s0[0] += v0.x; s0[1] += v0.y; s0[2] += v0.z; s0[3] += v0.w;
        s1[0] += v1.x; s1[1] += v1.y; s1[2] += v1.z; s1[3] += v1.w;
        q0[0] = fmaf(v0.x, v0.x, q0[0]); q0[1] = fmaf(v0.y, v0.y, q0[1]);
        q0[2] = fmaf(v0.z, v0.z, q0[2]); q0[3] = fmaf(v0.w, v0.w, q0[3]);
        q1[0] = fmaf(v1.x, v1.x, q1[0]); q1[1] = fmaf(v1.y, v1.y, q1[1]);
        q1[2] = fmaf(v1.z, v1.z, q1[2]); q1[3] = fmaf(v1.w, v1.w, q1[3]);
    }

    // Combine the 8 k-slices (consecutive lanes) via butterfly shuffles.
    #pragma unroll
    for (int o = 1; o < 8; o <<= 1) {
        #pragma unroll
        for (int c = 0; c < 4; c++) {
            s0[c] += __shfl_xor_sync(0xffffffffu, s0[c], o);
            s1[c] += __shfl_xor_sync(0xffffffffu, s1[c], o);
            q0[c] += __shfl_xor_sync(0xffffffffu, q0[c], o);
            q1[c] += __shfl_xor_sync(0xffffffffu, q1[c], o);
        }
    }

    float acc = 0.0f;
    if (j == 0) {
        const float invK  = 1.0f / (float)TOP_K;
        const float invK1 = 1.0f / (float)(TOP_K - 1);
        #pragma unroll
        for (int c = 0; c < 4; c++) {
            float mean = s0[c] * invK;
            float var  = fmaxf((q0[c] - s0[c] * mean) * invK1, 0.0f);
            acc = fmaf(sqrtf(var), __ldg(proj_w + 8 * g + c), acc);
            mean = s1[c] * invK;
            var  = fmaxf((q1[c] - s1[c] * mean) * invK1, 0.0f);
            acc = fmaf(sqrtf(var), __ldg(proj_w + 8 * g + 4 + c), acc);
        }
    }

    // ---- Phase B: simi + score feature groups ----
    const float* wS  = proj_w + EMB_DIM;                // simi
    const float* wD  = proj_w + EMB_DIM + TOP_K;        // |rot - stelp|
    const float* wA  = proj_w + EMB_DIM + 2 * TOP_K;    // stelp + rot
    const float* wSt = proj_w + EMB_DIM + 3 * TOP_K;    // stelp
    const float* wR  = proj_w + EMB_DIM + 4 * TOP_K;    // rot
    for (int k = tid; k < TOP_K; k += 768) {
        float ss = stelp_scores[b * TOP_K + k];
        float rr = rotate_scores[b * TOP_K + k];
        float sm = g_simi_mean[s_idx[k]];
        acc = fmaf(wS[k],  sm,             acc);
        acc = fmaf(wD[k],  fabsf(rr - ss), acc);
        acc = fmaf(wA[k],  ss + rr,        acc);
        acc = fmaf(wSt[k], ss,             acc);
        acc = fmaf(wR[k],  rr,             acc);
    }

    float total = block_reduce_sum(acc, sh);
    if (tid == 0) {
        float z = total + proj_b[0];
        g_alpha[b] = 1.0f / (1.0f + __expf(-z));
    }
}

// ---------------------------------------------------------------------------
// Kernel 3: margin ranking loss. Single block.
// ---------------------------------------------------------------------------
__global__ void loss_kernel(const float* __restrict__ pos_s,
                            const float* __restrict__ pos_r,
                            const float* __restrict__ neg_s,
                            const float* __restrict__ neg_r,
                            float* __restrict__ out) {
    __shared__ float sh[8];
    float acc = 0.f;
    for (int i = threadIdx.x; i < BS * NEG_T; i += blockDim.x) {
        int b = i / NEG_T;
        float a  = g_alpha[b];
        float pe = a * pos_s[b] + (1.0f - a) * pos_r[b];
        float ne = a * neg_s[i] + (1.0f - a) * neg_r[i];
        acc += fmaxf(MARGIN - pe + ne, 0.0f);
    }
    float total = block_reduce_sum(acc, sh);
    if (threadIdx.x == 0) out[0] = total * (1.0f / (float)(BS * NEG_T));
}

// ---------------------------------------------------------------------------
extern "C" void kernel_launch(void* const* d_in, const int* in_sizes, int n_in,
                              void* d_out, int out_size) {
    const float* pos_stelp  = (const float*)d_in[0];
    const float* pos_rotate = (const float*)d_in[1];
    const int*   ent_idx    = (const int*)  d_in[2];
    const float* neg_stelp  = (const float*)d_in[3];
    const float* neg_rotate = (const float*)d_in[4];
    const float* stelp_sc   = (const float*)d_in[5];
    const float* rotate_sc  = (const float*)d_in[6];
    const float* ent_emb    = (const float*)d_in[7];
    const float* simi_mtx   = (const float*)d_in[8];
    const float* proj_w     = (const float*)d_in[9];
    const float* proj_b     = (const float*)d_in[10];
    float* out = (float*)d_out;

    row_mean_kernel<<<N_ENT, 256>>>(simi_mtx);
    alpha_kernel<<<BS, 768>>>(ent_idx, stelp_sc, rotate_sc,
                              ent_emb, proj_w, proj_b);
    loss_kernel<<<1, 256>>>(pos_stelp, pos_rotate, neg_stelp, neg_rotate, out);
}

// round 5
// speedup vs baseline: 1.5021x; 1.5021x over previous
#include <cuda_runtime.h>
#include <math.h>

#define N_ENT   14541
#define EMB_DIM 768
#define EMB_V4  192            // EMB_DIM / 4
#define TOP_K   1000
#define NEG_T   5
#define BS      128
#define MARGIN  0.5f

// Scratch (no cudaMalloc allowed)
__device__ float g_simi_mean[N_ENT];
__device__ float g_accA[BS];     // Phase-A (emb std) contribution to the logit
__device__ float g_alpha[BS];

// ---------------------------------------------------------------------------
// Block reduce: valid result in thread 0.
// ---------------------------------------------------------------------------
__device__ __forceinline__ float block_reduce_sum(float v, float* sh) {
    #pragma unroll
    for (int o = 16; o > 0; o >>= 1) v += __shfl_down_sync(0xffffffffu, v, o);
    int wid = threadIdx.x >> 5;
    int lid = threadIdx.x & 31;
    if (lid == 0) sh[wid] = v;
    __syncthreads();
    int nw = blockDim.x >> 5;
    if (wid == 0) {
        v = (lid < nw) ? sh[lid] : 0.0f;
        #pragma unroll
        for (int o = 16; o > 0; o >>= 1) v += __shfl_down_sync(0xffffffffu, v, o);
    }
    return v;
}

// ---------------------------------------------------------------------------
// Fused kernel 1:
//   blocks [0, BS):            alpha Phase A (emb-std gather; L2-bound;
//                              independent of row means) -> g_accA[b]
//   blocks [BS, BS + N_ENT):   per-row mean of simi_score_mtx (DRAM-bound,
//                              __ldcs streaming so emb table stays L2-resident)
// Alpha blocks are scheduled first (wave 1) and hide under the DRAM stream.
// ---------------------------------------------------------------------------
__global__ __launch_bounds__(256)
void fused_kernel(const float* __restrict__ simi,
                  const int*   __restrict__ ent_idx,
                  const float* __restrict__ emb,
                  const float* __restrict__ proj_w) {
    __shared__ int   s_idx[TOP_K];
    __shared__ float sh[8];
    const int tid = threadIdx.x;

    if (blockIdx.x < BS) {
        // ================= alpha Phase A =================
        const int b = blockIdx.x;
        for (int k = tid; k < TOP_K; k += 256)
            s_idx[k] = ent_idx[b * TOP_K + k];
        __syncthreads();

        float acc = 0.0f;
        if (tid < EMB_V4) {
            // Thread tid owns dims [4*tid, 4*tid+4). A warp = 32 consecutive
            // float4s of the SAME row -> fully coalesced 512B bursts.
            const float4* __restrict__ emb4 = (const float4*)emb;
            float s0 = 0.f, s1 = 0.f, s2 = 0.f, s3 = 0.f;
            float q0 = 0.f, q1 = 0.f, q2 = 0.f, q3 = 0.f;
            #pragma unroll 4
            for (int k = 0; k < TOP_K; k++) {
                float4 v = __ldg(emb4 + (size_t)s_idx[k] * EMB_V4 + tid);
                s0 += v.x; s1 += v.y; s2 += v.z; s3 += v.w;
                q0 = fmaf(v.x, v.x, q0); q1 = fmaf(v.y, v.y, q1);
                q2 = fmaf(v.z, v.z, q2); q3 = fmaf(v.w, v.w, q3);
            }
            const float invK  = 1.0f / (float)TOP_K;
            const float invK1 = 1.0f / (float)(TOP_K - 1);
            float ss[4] = {s0, s1, s2, s3};
            float qq[4] = {q0, q1, q2, q3};
            #pragma unroll
            for (int c = 0; c < 4; c++) {
                float mean = ss[c] * invK;
                float var  = fmaxf((qq[c] - ss[c] * mean) * invK1, 0.0f);
                acc = fmaf(sqrtf(var), __ldg(proj_w + 4 * tid + c), acc);
            }
        }
        float total = block_reduce_sum(acc, sh);
        if (tid == 0) g_accA[b] = total;
    } else {
        // ================= row mean (streaming .cs loads) =================
        const int r = blockIdx.x - BS;
        const size_t e0 = (size_t)r * N_ENT;
        const size_t e1 = e0 + N_ENT;
        const size_t a0 = (e0 + 3) & ~(size_t)3;   // first 16B-aligned element
        const size_t a1 = e1 & ~(size_t)3;

        float s = 0.0f;
        for (size_t e = e0 + tid; e < a0; e += 256) s += __ldcs(simi + e);
        for (size_t e = a1 + tid; e < e1; e += 256) s += __ldcs(simi + e);

        const float4* __restrict__ v4 = (const float4*)(simi + a0);
        const int nv = (int)((a1 - a0) >> 2);
        float4 a = make_float4(0.f, 0.f, 0.f, 0.f);
        #pragma unroll 4
        for (int i = tid; i < nv; i += 256) {
            float4 x = __ldcs(v4 + i);
            a.x += x.x; a.y += x.y; a.z += x.z; a.w += x.w;
        }
        s += (a.x + a.y) + (a.z + a.w);
        s = block_reduce_sum(s, sh);
        if (tid == 0) g_simi_mean[r] = s * (1.0f / (float)N_ENT);
    }
}

// ---------------------------------------------------------------------------
// Kernel 2: alpha Phase B + sigmoid. One block (256 threads) per sample.
// ---------------------------------------------------------------------------
__global__ __launch_bounds__(256)
void phaseB_kernel(const int*   __restrict__ ent_idx,
                   const float* __restrict__ stelp_scores,
                   const float* __restrict__ rotate_scores,
                   const float* __restrict__ proj_w,
                   const float* __restrict__ proj_b) {
    __shared__ float sh[8];
    const int b   = blockIdx.x;
    const int tid = threadIdx.x;

    const float* wS  = proj_w + EMB_DIM;                // simi
    const float* wD  = proj_w + EMB_DIM + TOP_K;        // |rot - stelp|
    const float* wA  = proj_w + EMB_DIM + 2 * TOP_K;    // stelp + rot
    const float* wSt = proj_w + EMB_DIM + 3 * TOP_K;    // stelp
    const float* wR  = proj_w + EMB_DIM + 4 * TOP_K;    // rot

    float acc = 0.0f;
    for (int k = tid; k < TOP_K; k += 256) {
        int   ix = ent_idx[b * TOP_K + k];
        float ss = stelp_scores[b * TOP_K + k];
        float rr = rotate_scores[b * TOP_K + k];
        float sm = g_simi_mean[ix];
        acc = fmaf(wS[k],  sm,             acc);
        acc = fmaf(wD[k],  fabsf(rr - ss), acc);
        acc = fmaf(wA[k],  ss + rr,        acc);
        acc = fmaf(wSt[k], ss,             acc);
        acc = fmaf(wR[k],  rr,             acc);
    }
    float total = block_reduce_sum(acc, sh);
    if (tid == 0) {
        float z = total + g_accA[b] + proj_b[0];
        g_alpha[b] = 1.0f / (1.0f + __expf(-z));
    }
}

// ---------------------------------------------------------------------------
// Kernel 3: margin ranking loss. Single block.
// ---------------------------------------------------------------------------
__global__ void loss_kernel(const float* __restrict__ pos_s,
                            const float* __restrict__ pos_r,
                            const float* __restrict__ neg_s,
                            const float* __restrict__ neg_r,
                            float* __restrict__ out) {
    __shared__ float sh[8];
    float acc = 0.f;
    for (int i = threadIdx.x; i < BS * NEG_T; i += blockDim.x) {
        int b = i / NEG_T;
        float a  = g_alpha[b];
        float pe = a * pos_s[b] + (1.0f - a) * pos_r[b];
        float ne = a * neg_s[i] + (1.0f - a) * neg_r[i];
        acc += fmaxf(MARGIN - pe + ne, 0.0f);
    }
    float total = block_reduce_sum(acc, sh);
    if (threadIdx.x == 0) out[0] = total * (1.0f / (float)(BS * NEG_T));
}

// ---------------------------------------------------------------------------
extern "C" void kernel_launch(void* const* d_in, const int* in_sizes, int n_in,
                              void* d_out, int out_size) {
    const float* pos_stelp  = (const float*)d_in[0];
    const float* pos_rotate = (const float*)d_in[1];
    const int*   ent_idx    = (const int*)  d_in[2];
    const float* neg_stelp  = (const float*)d_in[3];
    const float* neg_rotate = (const float*)d_in[4];
    const float* stelp_sc   = (const float*)d_in[5];
    const float* rotate_sc  = (const float*)d_in[6];
    const float* ent_emb    = (const float*)d_in[7];
    const float* simi_mtx   = (const float*)d_in[8];
    const float* proj_w     = (const float*)d_in[9];
    const float* proj_b     = (const float*)d_in[10];
    float* out = (float*)d_out;

    fused_kernel<<<BS + N_ENT, 256>>>(simi_mtx, ent_idx, ent_emb, proj_w);
    phaseB_kernel<<<BS, 256>>>(ent_idx, stelp_sc, rotate_sc, proj_w, proj_b);
    loss_kernel<<<1, 256>>>(pos_stelp, pos_rotate, neg_stelp, neg_rotate, out);
}

// round 6
// speedup vs baseline: 1.6487x; 1.0976x over previous
#include <cuda_runtime.h>
#include <math.h>

#define N_ENT   14541
#define EMB_DIM 768
#define EMB_V4  192            // EMB_DIM / 4
#define TOP_K   1000
#define NEG_T   5
#define BS      128
#define MARGIN  0.5f

#define KSLICES 4
#define KSEG    (TOP_K / KSLICES)      // 250
#define A_BLKS  (BS * KSLICES)         // 512 alpha partial blocks

// Scratch (no cudaMalloc allowed)
__device__ float g_simi_mean[N_ENT];
__device__ float4 g_psum[A_BLKS * EMB_V4];   // per (block, dim-group) partial sums
__device__ float4 g_psq [A_BLKS * EMB_V4];   // per (block, dim-group) partial sumsq
__device__ float g_alpha[BS];

// ---------------------------------------------------------------------------
// Block reduce: valid result in thread 0.
// ---------------------------------------------------------------------------
__device__ __forceinline__ float block_reduce_sum(float v, float* sh) {
    #pragma unroll
    for (int o = 16; o > 0; o >>= 1) v += __shfl_down_sync(0xffffffffu, v, o);
    int wid = threadIdx.x >> 5;
    int lid = threadIdx.x & 31;
    if (lid == 0) sh[wid] = v;
    __syncthreads();
    int nw = blockDim.x >> 5;
    if (wid == 0) {
        v = (lid < nw) ? sh[lid] : 0.0f;
        #pragma unroll
        for (int o = 16; o > 0; o >>= 1) v += __shfl_down_sync(0xffffffffu, v, o);
    }
    return v;
}

// ---------------------------------------------------------------------------
// Fused kernel 1:
//   blocks [0, A_BLKS):          alpha Phase A partials. Block (b, slice)
//       gathers emb rows for k in [slice*250, slice*250+250) and writes raw
//       per-dim-group float4 sum/sumsq partials (no reduction, no atomics).
//       4x shorter-lived than one-block-per-sample -> small interference
//       window against the DRAM stream.
//   blocks [A_BLKS, A_BLKS+N_ENT): per-row mean of simi_score_mtx
//       (DRAM-bound, __ldcs streaming so the emb table stays L2-resident).
// ---------------------------------------------------------------------------
__global__ __launch_bounds__(256)
void fused_kernel(const float* __restrict__ simi,
                  const int*   __restrict__ ent_idx,
                  const float* __restrict__ emb) {
    __shared__ int   s_idx[KSEG];
    __shared__ float sh[8];
    const int tid = threadIdx.x;

    if (blockIdx.x < A_BLKS) {
        // ================= alpha Phase A partial =================
        const int b     = blockIdx.x >> 2;       // sample
        const int slice = blockIdx.x & 3;        // k-slice
        const int k0    = slice * KSEG;

        for (int k = tid; k < KSEG; k += 256)
            s_idx[k] = ent_idx[b * TOP_K + k0 + k];
        __syncthreads();

        if (tid < EMB_V4) {
            // Thread tid owns dims [4*tid, 4*tid+4). A warp = 32 consecutive
            // float4s of the SAME row -> fully coalesced 512B bursts.
            const float4* __restrict__ emb4 = (const float4*)emb;
            float s0 = 0.f, s1 = 0.f, s2 = 0.f, s3 = 0.f;
            float q0 = 0.f, q1 = 0.f, q2 = 0.f, q3 = 0.f;
            #pragma unroll 5
            for (int k = 0; k < KSEG; k++) {
                float4 v = __ldg(emb4 + (size_t)s_idx[k] * EMB_V4 + tid);
                s0 += v.x; s1 += v.y; s2 += v.z; s3 += v.w;
                q0 = fmaf(v.x, v.x, q0); q1 = fmaf(v.y, v.y, q1);
                q2 = fmaf(v.z, v.z, q2); q3 = fmaf(v.w, v.w, q3);
            }
            g_psum[blockIdx.x * EMB_V4 + tid] = make_float4(s0, s1, s2, s3);
            g_psq [blockIdx.x * EMB_V4 + tid] = make_float4(q0, q1, q2, q3);
        }
    } else {
        // ================= row mean (streaming .cs loads) =================
        const int r = blockIdx.x - A_BLKS;
        const size_t e0 = (size_t)r * N_ENT;
        const size_t e1 = e0 + N_ENT;
        const size_t a0 = (e0 + 3) & ~(size_t)3;   // first 16B-aligned element
        const size_t a1 = e1 & ~(size_t)3;

        float s = 0.0f;
        for (size_t e = e0 + tid; e < a0; e += 256) s += __ldcs(simi + e);
        for (size_t e = a1 + tid; e < e1; e += 256) s += __ldcs(simi + e);

        const float4* __restrict__ v4 = (const float4*)(simi + a0);
        const int nv = (int)((a1 - a0) >> 2);
        float4 a = make_float4(0.f, 0.f, 0.f, 0.f);
        #pragma unroll 4
        for (int i = tid; i < nv; i += 256) {
            float4 x = __ldcs(v4 + i);
            a.x += x.x; a.y += x.y; a.z += x.z; a.w += x.w;
        }
        s += (a.x + a.y) + (a.z + a.w);
        s = block_reduce_sum(s, sh);
        if (tid == 0) g_simi_mean[r] = s * (1.0f / (float)N_ENT);
    }
}

// ---------------------------------------------------------------------------
// Kernel 2: combine Phase-A partials (std * w) + Phase B + sigmoid.
// One block (256 threads) per sample.
// ---------------------------------------------------------------------------
__global__ __launch_bounds__(256)
void phaseB_kernel(const int*   __restrict__ ent_idx,
                   const float* __restrict__ stelp_scores,
                   const float* __restrict__ rotate_scores,
                   const float* __restrict__ proj_w,
                   const float* __restrict__ proj_b) {
    __shared__ float sh[8];
    const int b   = blockIdx.x;
    const int tid = threadIdx.x;

    float acc = 0.0f;

    // ---- combine the 4 k-slice partials, compute std(ddof=1) dot w ----
    if (tid < EMB_V4) {
        float4 S = make_float4(0.f, 0.f, 0.f, 0.f);
        float4 Q = make_float4(0.f, 0.f, 0.f, 0.f);
        #pragma unroll
        for (int s = 0; s < KSLICES; s++) {
            int pb = (b << 2) + s;
            float4 ps = g_psum[pb * EMB_V4 + tid];
            float4 pq = g_psq [pb * EMB_V4 + tid];
            S.x += ps.x; S.y += ps.y; S.z += ps.z; S.w += ps.w;
            Q.x += pq.x; Q.y += pq.y; Q.z += pq.z; Q.w += pq.w;
        }
        const float invK  = 1.0f / (float)TOP_K;
        const float invK1 = 1.0f / (float)(TOP_K - 1);
        float ss[4] = {S.x, S.y, S.z, S.w};
        float qq[4] = {Q.x, Q.y, Q.z, Q.w};
        #pragma unroll
        for (int c = 0; c < 4; c++) {
            float mean = ss[c] * invK;
            float var  = fmaxf((qq[c] - ss[c] * mean) * invK1, 0.0f);
            acc = fmaf(sqrtf(var), __ldg(proj_w + 4 * tid + c), acc);
        }
    }

    // ---- Phase B: simi + score feature groups ----
    const float* wS  = proj_w + EMB_DIM;                // simi
    const float* wD  = proj_w + EMB_DIM + TOP_K;        // |rot - stelp|
    const float* wA  = proj_w + EMB_DIM + 2 * TOP_K;    // stelp + rot
    const float* wSt = proj_w + EMB_DIM + 3 * TOP_K;    // stelp
    const float* wR  = proj_w + EMB_DIM + 4 * TOP_K;    // rot

    for (int k = tid; k < TOP_K; k += 256) {
        int   ix = ent_idx[b * TOP_K + k];
        float ss = stelp_scores[b * TOP_K + k];
        float rr = rotate_scores[b * TOP_K + k];
        float sm = g_simi_mean[ix];
        acc = fmaf(wS[k],  sm,             acc);
        acc = fmaf(wD[k],  fabsf(rr - ss), acc);
        acc = fmaf(wA[k],  ss + rr,        acc);
        acc = fmaf(wSt[k], ss,             acc);
        acc = fmaf(wR[k],  rr,             acc);
    }
    float total = block_reduce_sum(acc, sh);
    if (tid == 0) {
        float z = total + proj_b[0];
        g_alpha[b] = 1.0f / (1.0f + __expf(-z));
    }
}

// ---------------------------------------------------------------------------
// Kernel 3: margin ranking loss. Single block.
// ---------------------------------------------------------------------------
__global__ void loss_kernel(const float* __restrict__ pos_s,
                            const float* __restrict__ pos_r,
                            const float* __restrict__ neg_s,
                            const float* __restrict__ neg_r,
                            float* __restrict__ out) {
    __shared__ float sh[8];
    float acc = 0.f;
    for (int i = threadIdx.x; i < BS * NEG_T; i += blockDim.x) {
        int b = i / NEG_T;
        float a  = g_alpha[b];
        float pe = a * pos_s[b] + (1.0f - a) * pos_r[b];
        float ne = a * neg_s[i] + (1.0f - a) * neg_r[i];
        acc += fmaxf(MARGIN - pe + ne, 0.0f);
    }
    float total = block_reduce_sum(acc, sh);
    if (threadIdx.x == 0) out[0] = total * (1.0f / (float)(BS * NEG_T));
}

// ---------------------------------------------------------------------------
extern "C" void kernel_launch(void* const* d_in, const int* in_sizes, int n_in,
                              void* d_out, int out_size) {
    const float* pos_stelp  = (const float*)d_in[0];
    const float* pos_rotate = (const float*)d_in[1];
    const int*   ent_idx    = (const int*)  d_in[2];
    const float* neg_stelp  = (const float*)d_in[3];
    const float* neg_rotate = (const float*)d_in[4];
    const float* stelp_sc   = (const float*)d_in[5];
    const float* rotate_sc  = (const float*)d_in[6];
    const float* ent_emb    = (const float*)d_in[7];
    const float* simi_mtx   = (const float*)d_in[8];
    const float* proj_w     = (const float*)d_in[9];
    const float* proj_b     = (const float*)d_in[10];
    float* out = (float*)d_out;

    fused_kernel<<<A_BLKS + N_ENT, 256>>>(simi_mtx, ent_idx, ent_emb);
    phaseB_kernel<<<BS, 256>>>(ent_idx, stelp_sc, rotate_sc, proj_w, proj_b);
    loss_kernel<<<1, 256>>>(pos_stelp, pos_rotate, neg_stelp, neg_rotate, out);
}